// round 2
// baseline (speedup 1.0000x reference)
#include <cuda_runtime.h>
#include <cstdint>

#define NB 4
#define NS 4096
#define ND 4096
#define NE 64
#define NTOK (NB * NS)        // 16384
#define TM 128                // tokens per CTA
#define TK 32                 // K per smem stage
#define NTHREADS 256
#define KSTAGES (ND / TK)     // 128

// smem: h[2][TK][TM] (16KB*2) + w[2][TK][NE] (8KB*2) = 49152 B (static limit exact)
// epilogue reuses the same buffer as logits[TM][65] (33.3 KB)
#define SMEM_FLOATS (2 * TK * TM + 2 * TK * NE)

__global__ __launch_bounds__(NTHREADS)
void topk_router_kernel(const float* __restrict__ hs,
                        const float* __restrict__ W,
                        float* __restrict__ out)
{
    __shared__ __align__(16) float smem[SMEM_FLOATS];
    float* hS = smem;                       // [2][TK][TM]
    float* wS = smem + 2 * TK * TM;         // [2][TK][NE]

    const int tid = threadIdx.x;
    const int tx  = tid & 31;               // token lane (0..31)
    const int ty  = tid >> 5;               // expert group / warp (0..7)
    const int tok0 = blockIdx.x * TM;

    // ---- loader index maps (coalesced 128B rows) ----
    const int h_c4 = tid & 7;               // float4 column within 32-wide K chunk
    const int h_r0 = tid >> 3;              // token row 0..31 (4 passes of +32)
    const int w_c4 = tid & 7;
    const int w_e0 = tid >> 3;              // expert row 0..31 (2 passes of +32)

    float4 hreg[4];
    float4 wreg[2];

    // accumulators: 4 tokens (tx + 32*i) x 4 expert-PAIRS (e0 = ty*8 + 2p), packed f32x2
    unsigned long long acc[4][4];
#pragma unroll
    for (int i = 0; i < 4; i++)
#pragma unroll
        for (int p = 0; p < 4; p++) acc[i][p] = 0ull;

    // ---- stage 0 load + store ----
    {
        const float* hp = hs + (size_t)tok0 * ND;
#pragma unroll
        for (int r = 0; r < 4; r++)
            hreg[r] = *(const float4*)(hp + (size_t)(h_r0 + 32 * r) * ND + h_c4 * 4);
#pragma unroll
        for (int p = 0; p < 2; p++)
            wreg[p] = *(const float4*)(W + (size_t)(w_e0 + 32 * p) * ND + w_c4 * 4);
    }
#pragma unroll
    for (int r = 0; r < 4; r++) {
        int t = h_r0 + 32 * r;
        hS[(h_c4 * 4 + 0) * TM + t] = hreg[r].x;
        hS[(h_c4 * 4 + 1) * TM + t] = hreg[r].y;
        hS[(h_c4 * 4 + 2) * TM + t] = hreg[r].z;
        hS[(h_c4 * 4 + 3) * TM + t] = hreg[r].w;
    }
#pragma unroll
    for (int p = 0; p < 2; p++) {
        int e = w_e0 + 32 * p;
        wS[(w_c4 * 4 + 0) * NE + e] = wreg[p].x;
        wS[(w_c4 * 4 + 1) * NE + e] = wreg[p].y;
        wS[(w_c4 * 4 + 2) * NE + e] = wreg[p].z;
        wS[(w_c4 * 4 + 3) * NE + e] = wreg[p].w;
    }
    __syncthreads();

    // ---- main K loop, double buffered ----
    for (int s = 0; s < KSTAGES; s++) {
        if (s + 1 < KSTAGES) {
            const int ks = s + 1;
            const float* hp = hs + (size_t)tok0 * ND + ks * TK;
#pragma unroll
            for (int r = 0; r < 4; r++)
                hreg[r] = *(const float4*)(hp + (size_t)(h_r0 + 32 * r) * ND + h_c4 * 4);
#pragma unroll
            for (int p = 0; p < 2; p++)
                wreg[p] = *(const float4*)(W + (size_t)(w_e0 + 32 * p) * ND + ks * TK + w_c4 * 4);
        }

        {
            const float* hb = hS + (s & 1) * TK * TM;
            const float* wb = wS + (s & 1) * TK * NE;
#pragma unroll
            for (int k = 0; k < TK; k++) {
                unsigned long long hd[4];
#pragma unroll
                for (int i = 0; i < 4; i++) {
                    float hv = hb[k * TM + tx + 32 * i];
                    asm("mov.b64 %0, {%1, %1};" : "=l"(hd[i]) : "f"(hv));
                }
                const unsigned long long* wp =
                    reinterpret_cast<const unsigned long long*>(wb + k * NE + ty * 8);
                unsigned long long w2[4];
#pragma unroll
                for (int p = 0; p < 4; p++) w2[p] = wp[p];
#pragma unroll
                for (int i = 0; i < 4; i++)
#pragma unroll
                    for (int p = 0; p < 4; p++)
                        asm("fma.rn.f32x2 %0, %1, %2, %0;"
                            : "+l"(acc[i][p]) : "l"(hd[i]), "l"(w2[p]));
            }
        }
        __syncthreads();

        if (s + 1 < KSTAGES) {
            const int buf = (s + 1) & 1;
#pragma unroll
            for (int r = 0; r < 4; r++) {
                int t = h_r0 + 32 * r;
                hS[buf * TK * TM + (h_c4 * 4 + 0) * TM + t] = hreg[r].x;
                hS[buf * TK * TM + (h_c4 * 4 + 1) * TM + t] = hreg[r].y;
                hS[buf * TK * TM + (h_c4 * 4 + 2) * TM + t] = hreg[r].z;
                hS[buf * TK * TM + (h_c4 * 4 + 3) * TM + t] = hreg[r].w;
            }
#pragma unroll
            for (int p = 0; p < 2; p++) {
                int e = w_e0 + 32 * p;
                wS[buf * TK * NE + (w_c4 * 4 + 0) * NE + e] = wreg[p].x;
                wS[buf * TK * NE + (w_c4 * 4 + 1) * NE + e] = wreg[p].y;
                wS[buf * TK * NE + (w_c4 * 4 + 2) * NE + e] = wreg[p].z;
                wS[buf * TK * NE + (w_c4 * 4 + 3) * NE + e] = wreg[p].w;
            }
            __syncthreads();
        }
    }

    // ---- epilogue: logits -> smem (stride 65, conflict-free scan), top-2 + softmax ----
    __syncthreads();
    float* LG = smem;  // [TM][65]
#pragma unroll
    for (int i = 0; i < 4; i++) {
        int t = tx + 32 * i;
#pragma unroll
        for (int p = 0; p < 4; p++) {
            float lo, hi;
            asm("mov.b64 {%0, %1}, %2;" : "=f"(lo), "=f"(hi) : "l"(acc[i][p]));
            int e = ty * 8 + 2 * p;
            LG[t * 65 + e]     = lo;
            LG[t * 65 + e + 1] = hi;
        }
    }
    __syncthreads();

    if (tid < TM) {
        const int t = tid;
        float m1 = -3.4e38f, m2 = -3.4e38f;
        int i1 = 0, i2 = 0;
#pragma unroll 8
        for (int e = 0; e < NE; e++) {
            float v = LG[t * 65 + e];
            if (v > m1) { m2 = m1; i2 = i1; m1 = v; i1 = e; }
            else if (v > m2) { m2 = v; i2 = e; }
        }
        float ex = __expf(m2 - m1);           // fast exp; |err| ~1e-6 rel, fine at 1e-3 tol
        float s1 = 1.0f / (1.0f + ex);
        float s2 = ex * s1;
        int tg = tok0 + t;
        out[2 * tg]     = s1;
        out[2 * tg + 1] = s2;
        out[2 * NTOK + 2 * tg]     = (float)i1;
        out[2 * NTOK + 2 * tg + 1] = (float)i2;
    }
}

extern "C" void kernel_launch(void* const* d_in, const int* in_sizes, int n_in,
                              void* d_out, int out_size)
{
    const float* hs = (const float*)d_in[0];   // (4, 4096, 4096) fp32
    const float* W  = (const float*)d_in[1];   // (64, 4096) fp32
    float* out      = (float*)d_out;           // [scores 32768][indices 32768]
    (void)in_sizes; (void)n_in; (void)out_size;

    topk_router_kernel<<<NTOK / TM, NTHREADS>>>(hs, W, out);
}

// round 3
// speedup vs baseline: 1.1541x; 1.1541x over previous
#include <cuda_runtime.h>
#include <cstdint>

#define NB 4
#define NS 4096
#define ND 4096
#define NE 64
#define NTOK (NB * NS)        // 16384
#define TM 128                // tokens per CTA
#define TK 32                 // K per smem stage
#define NTHREADS 256
#define KSTAGES (ND / TK)     // 128
#define HPAD 33               // token-major h rows padded -> bank = (t+k)&31, conflict-free

// smem union: mainloop h[TM][HPAD] + w[TK][NE] = 4224+2048 = 6272 floats (25KB)
//             epilogue logits[TM][65] = 8320 floats (33.3KB)
#define SMEM_FLOATS (TM * 65)

__global__ __launch_bounds__(NTHREADS)
void topk_router_kernel(const float* __restrict__ hs,
                        const float* __restrict__ W,
                        float* __restrict__ out)
{
    __shared__ __align__(16) float smem[SMEM_FLOATS];
    float* hS = smem;               // [TM][HPAD]
    float* wS = smem + TM * HPAD;   // [TK][NE], expert index XOR-swizzled by 4*(k>>2)

    const int tid  = threadIdx.x;
    const int tok0 = blockIdx.x * TM;

    // loader maps (coalesced float4 rows; 8 lanes cover one 128B row-chunk)
    const int c4 = tid & 7;         // float4 column within 32-wide K chunk
    const int r0 = tid >> 3;        // row 0..31 (h: +32*r for 4 reps; w: +32*rep for 2 reps)

    // compute maps
    const int tx = tid & 63;        // token lane: tokens {tx, tx+64}
    const int ty = tid >> 6;        // expert group: e0 = ty*16 (16 experts = 8 pairs)
    const int e0 = ty * 16;

    float4 hreg[4];
    float4 wreg[2];

    // acc[token][pair] packed f32x2 over expert pairs (e0+2p, e0+2p+1)
    unsigned long long acc0[8], acc1[8];
#pragma unroll
    for (int p = 0; p < 8; p++) { acc0[p] = 0ull; acc1[p] = 0ull; }

    // ---- prologue: stage 0 ----
    {
        const float* hp = hs + (size_t)tok0 * ND + c4 * 4;
#pragma unroll
        for (int r = 0; r < 4; r++)
            hreg[r] = *(const float4*)(hp + (size_t)(r0 + 32 * r) * ND);
#pragma unroll
        for (int rep = 0; rep < 2; rep++)
            wreg[rep] = *(const float4*)(W + (size_t)(r0 + 32 * rep) * ND + c4 * 4);
    }
#pragma unroll
    for (int r = 0; r < 4; r++) {
        int t = r0 + 32 * r;
        hS[t * HPAD + c4 * 4 + 0] = hreg[r].x;
        hS[t * HPAD + c4 * 4 + 1] = hreg[r].y;
        hS[t * HPAD + c4 * 4 + 2] = hreg[r].z;
        hS[t * HPAD + c4 * 4 + 3] = hreg[r].w;
    }
#pragma unroll
    for (int rep = 0; rep < 2; rep++) {
        int e  = r0 + 32 * rep;
        int es = e ^ (c4 * 4);      // store swizzle: bank = distinct across warp
        wS[(c4 * 4 + 0) * NE + es] = wreg[rep].x;
        wS[(c4 * 4 + 1) * NE + es] = wreg[rep].y;
        wS[(c4 * 4 + 2) * NE + es] = wreg[rep].z;
        wS[(c4 * 4 + 3) * NE + es] = wreg[rep].w;
    }
    __syncthreads();

    const float* h0p = hS + tx * HPAD;
    const float* h1p = hS + (tx + 64) * HPAD;

    // ---- main K loop ----
    for (int s = 0; s < KSTAGES; s++) {
        if (s + 1 < KSTAGES) {
            const int ko = (s + 1) * TK;
            const float* hp = hs + (size_t)tok0 * ND + ko + c4 * 4;
#pragma unroll
            for (int r = 0; r < 4; r++)
                hreg[r] = *(const float4*)(hp + (size_t)(r0 + 32 * r) * ND);
#pragma unroll
            for (int rep = 0; rep < 2; rep++)
                wreg[rep] = *(const float4*)(W + (size_t)(r0 + 32 * rep) * ND + ko + c4 * 4);
        }

#pragma unroll
        for (int k = 0; k < TK; k++) {
            float a0 = h0p[k];
            float a1 = h1p[k];
            unsigned long long d0, d1;
            asm("mov.b64 %0, {%1, %1};" : "=l"(d0) : "f"(a0));
            asm("mov.b64 %0, {%1, %1};" : "=l"(d1) : "f"(a1));
            const int sw = k & 28;  // compile-time constant per unrolled k
            unsigned long long w2[8];
#pragma unroll
            for (int p = 0; p < 8; p++)
                w2[p] = *reinterpret_cast<const unsigned long long*>(
                            wS + k * NE + ((e0 + 2 * p) ^ sw));
#pragma unroll
            for (int p = 0; p < 8; p++) {
                asm("fma.rn.f32x2 %0, %1, %2, %0;" : "+l"(acc0[p]) : "l"(d0), "l"(w2[p]));
                asm("fma.rn.f32x2 %0, %1, %2, %0;" : "+l"(acc1[p]) : "l"(d1), "l"(w2[p]));
            }
        }
        __syncthreads();

        if (s + 1 < KSTAGES) {
#pragma unroll
            for (int r = 0; r < 4; r++) {
                int t = r0 + 32 * r;
                hS[t * HPAD + c4 * 4 + 0] = hreg[r].x;
                hS[t * HPAD + c4 * 4 + 1] = hreg[r].y;
                hS[t * HPAD + c4 * 4 + 2] = hreg[r].z;
                hS[t * HPAD + c4 * 4 + 3] = hreg[r].w;
            }
#pragma unroll
            for (int rep = 0; rep < 2; rep++) {
                int e  = r0 + 32 * rep;
                int es = e ^ (c4 * 4);
                wS[(c4 * 4 + 0) * NE + es] = wreg[rep].x;
                wS[(c4 * 4 + 1) * NE + es] = wreg[rep].y;
                wS[(c4 * 4 + 2) * NE + es] = wreg[rep].z;
                wS[(c4 * 4 + 3) * NE + es] = wreg[rep].w;
            }
            __syncthreads();
        }
    }

    // ---- epilogue: logits -> smem (stride 65: bank = (t+e)&31 on the scan), top-2 + softmax ----
    float* LG = smem;  // [TM][65]
#pragma unroll
    for (int p = 0; p < 8; p++) {
        float lo, hi;
        int e = e0 + 2 * p;
        asm("mov.b64 {%0, %1}, %2;" : "=f"(lo), "=f"(hi) : "l"(acc0[p]));
        LG[tx * 65 + e]     = lo;
        LG[tx * 65 + e + 1] = hi;
        asm("mov.b64 {%0, %1}, %2;" : "=f"(lo), "=f"(hi) : "l"(acc1[p]));
        LG[(tx + 64) * 65 + e]     = lo;
        LG[(tx + 64) * 65 + e + 1] = hi;
    }
    __syncthreads();

    if (tid < TM) {
        const int t = tid;
        float m1 = -3.4e38f, m2 = -3.4e38f;
        int i1 = 0, i2 = 0;
#pragma unroll 8
        for (int e = 0; e < NE; e++) {
            float v = LG[t * 65 + e];
            if (v > m1) { m2 = m1; i2 = i1; m1 = v; i1 = e; }
            else if (v > m2) { m2 = v; i2 = e; }
        }
        float ex = __expf(m2 - m1);
        float s1 = 1.0f / (1.0f + ex);
        float s2 = ex * s1;
        int tg = tok0 + t;
        out[2 * tg]     = s1;
        out[2 * tg + 1] = s2;
        out[2 * NTOK + 2 * tg]     = (float)i1;
        out[2 * NTOK + 2 * tg + 1] = (float)i2;
    }
}

extern "C" void kernel_launch(void* const* d_in, const int* in_sizes, int n_in,
                              void* d_out, int out_size)
{
    const float* hs = (const float*)d_in[0];   // (4, 4096, 4096) fp32
    const float* W  = (const float*)d_in[1];   // (64, 4096) fp32
    float* out      = (float*)d_out;           // [scores 32768][indices 32768]
    (void)in_sizes; (void)n_in; (void)out_size;

    topk_router_kernel<<<NTOK / TM, NTHREADS>>>(hs, W, out);
}

// round 6
// speedup vs baseline: 1.5714x; 1.3615x over previous
#include <cuda_runtime.h>
#include <cstdint>

#define ND 4096
#define NE 64
#define NTOK 16384
#define TOK_CTA 64
#define NTHREADS 128
#define KC 64
#define NSTAGE (ND / KC)        // 64
#define PLANE 8192              // [4 g][64 n][4 j] * 8B
#define BUFB (3 * PLANE)        // hi, mid, lo planes

// round-to-nearest 3-way split: h = hi + mid + lo + eps, |eps| <= 2^-27|h|, unbiased.
// Subtractions are exact (Sterbenz); rn keeps residuals sign-symmetric so dropped
// cross terms random-walk instead of accumulating linearly.
__device__ __forceinline__ void cvt_split_pair(float h0, float h1,
                                               uint32_t& hi2, uint32_t& mid2, uint32_t& lo2) {
    asm("cvt.rn.bf16x2.f32 %0, %1, %2;" : "=r"(hi2) : "f"(h1), "f"(h0));   // lo half = h0
    float f0 = __uint_as_float(hi2 << 16);
    float f1 = __uint_as_float(hi2 & 0xFFFF0000u);
    float r0 = h0 - f0;
    float r1 = h1 - f1;
    asm("cvt.rn.bf16x2.f32 %0, %1, %2;" : "=r"(mid2) : "f"(r1), "f"(r0));
    float g0 = __uint_as_float(mid2 << 16);
    float g1 = __uint_as_float(mid2 & 0xFFFF0000u);
    float q0 = r0 - g0;
    float q1 = r1 - g1;
    asm("cvt.rn.bf16x2.f32 %0, %1, %2;" : "=r"(lo2) : "f"(q1), "f"(q0));
}

#define MMA(c, a, b0_, b1_) \
    asm volatile("mma.sync.aligned.m16n8k16.row.col.f32.bf16.bf16.f32 " \
        "{%0,%1,%2,%3}, {%4,%5,%6,%7}, {%8,%9}, {%0,%1,%2,%3};" \
        : "+f"((c)[0]), "+f"((c)[1]), "+f"((c)[2]), "+f"((c)[3]) \
        : "r"((a)[0]), "r"((a)[1]), "r"((a)[2]), "r"((a)[3]), "r"(b0_), "r"(b1_))

__global__ __launch_bounds__(NTHREADS, 2)
void topk_router_kernel(const float* __restrict__ hs,
                        const float* __restrict__ W,
                        float* __restrict__ out)
{
    __shared__ __align__(16) char smem[2 * BUFB];   // 49152 B exactly

    const int tid  = threadIdx.x;
    const int lane = tid & 31;
    const int warp = tid >> 5;
    const int j    = lane & 3;     // thread-in-group (k-pair selector)
    const int qr   = lane >> 2;    // group id (row / n selector)
    const int tok0 = blockIdx.x * TOK_CTA;

    // W-conversion slice: this thread owns (n, j) for n in {8*warp+qr, +32}, g = 0..3
    const int wn0 = 8 * warp + qr;

    // A row base: row = tok0 + warp*16 + qr (and +8), cols offset 2*j
    const float* aRow = hs + (size_t)(tok0 + warp * 16 + qr) * ND + 2 * j;

    float acc[8][4];
#pragma unroll
    for (int t = 0; t < 8; t++)
#pragma unroll
        for (int c = 0; c < 4; c++) acc[t][c] = 0.f;

    float2 wpre[16];

    // ---- prologue: load + convert W stage 0 into buf0 ----
#pragma unroll
    for (int h = 0; h < 2; h++) {
        const float* wr = W + (size_t)(wn0 + 32 * h) * ND + 2 * j;
#pragma unroll
        for (int g = 0; g < 4; g++) {
            wpre[h * 8 + g * 2 + 0] = *(const float2*)(wr + 16 * g);
            wpre[h * 8 + g * 2 + 1] = *(const float2*)(wr + 16 * g + 8);
        }
    }
#pragma unroll
    for (int h = 0; h < 2; h++) {
        int n = wn0 + 32 * h;
#pragma unroll
        for (int g = 0; g < 4; g++) {
            uint32_t h0, m0, l0, h1, m1, l1;
            float2 p0 = wpre[h * 8 + g * 2], p1 = wpre[h * 8 + g * 2 + 1];
            cvt_split_pair(p0.x, p0.y, h0, m0, l0);
            cvt_split_pair(p1.x, p1.y, h1, m1, l1);
            char* d = smem + (g * 64 + n) * 32 + j * 8;
            *(uint2*)(d)             = make_uint2(h0, h1);
            *(uint2*)(d + PLANE)     = make_uint2(m0, m1);
            *(uint2*)(d + 2 * PLANE) = make_uint2(l0, l1);
        }
    }
    __syncthreads();

    // ---- main loop over K stages ----
    for (int s = 0; s < NSTAGE; s++) {
        // prefetch W for stage s+1 into registers (hidden behind this stage's MMAs)
        if (s + 1 < NSTAGE) {
            const int kn = (s + 1) * KC;
#pragma unroll
            for (int h = 0; h < 2; h++) {
                const float* wr = W + (size_t)(wn0 + 32 * h) * ND + kn + 2 * j;
#pragma unroll
                for (int g = 0; g < 4; g++) {
                    wpre[h * 8 + g * 2 + 0] = *(const float2*)(wr + 16 * g);
                    wpre[h * 8 + g * 2 + 1] = *(const float2*)(wr + 16 * g + 8);
                }
            }
        }

        const char* buf = smem + (s & 1) * BUFB;
        const int k0 = s * KC;

        // rolling A fragment prefetch (fp32)
        float2 a0 = *(const float2*)(aRow + k0);
        float2 a1 = *(const float2*)(aRow + 8 * ND + k0);
        float2 a2 = *(const float2*)(aRow + k0 + 8);
        float2 a3 = *(const float2*)(aRow + 8 * ND + k0 + 8);

#pragma unroll
        for (int g = 0; g < 4; g++) {
            float2 p0, p1, p2, p3;
            if (g < 3) {
                const int kg = k0 + 16 * (g + 1);
                p0 = *(const float2*)(aRow + kg);
                p1 = *(const float2*)(aRow + 8 * ND + kg);
                p2 = *(const float2*)(aRow + kg + 8);
                p3 = *(const float2*)(aRow + 8 * ND + kg + 8);
            }
            uint32_t aH[4], aM[4], aL[4];
            cvt_split_pair(a0.x, a0.y, aH[0], aM[0], aL[0]);
            cvt_split_pair(a1.x, a1.y, aH[1], aM[1], aL[1]);
            cvt_split_pair(a2.x, a2.y, aH[2], aM[2], aL[2]);
            cvt_split_pair(a3.x, a3.y, aH[3], aM[3], aL[3]);

            const char* bb = buf + (size_t)(g * 64 + qr) * 32 + j * 8;
#pragma unroll
            for (int t = 0; t < 8; t++) {
                const char* bt = bb + t * 256;            // +8 n rows
                uint2 bh = *(const uint2*)(bt);
                uint2 bm = *(const uint2*)(bt + PLANE);
                uint2 bl = *(const uint2*)(bt + 2 * PLANE);
                MMA(acc[t], aH, bh.x, bh.y);
                MMA(acc[t], aM, bh.x, bh.y);
                MMA(acc[t], aL, bh.x, bh.y);
                MMA(acc[t], aH, bm.x, bm.y);
                MMA(acc[t], aM, bm.x, bm.y);
                MMA(acc[t], aH, bl.x, bl.y);
            }
            if (g < 3) { a0 = p0; a1 = p1; a2 = p2; a3 = p3; }
        }

        // convert prefetched W into the other buffer, then stage barrier
        if (s + 1 < NSTAGE) {
            char* nb = smem + ((s + 1) & 1) * BUFB;
#pragma unroll
            for (int h = 0; h < 2; h++) {
                int n = wn0 + 32 * h;
#pragma unroll
                for (int g = 0; g < 4; g++) {
                    uint32_t h0, m0, l0, h1, m1, l1;
                    float2 p0 = wpre[h * 8 + g * 2], p1 = wpre[h * 8 + g * 2 + 1];
                    cvt_split_pair(p0.x, p0.y, h0, m0, l0);
                    cvt_split_pair(p1.x, p1.y, h1, m1, l1);
                    char* d = nb + (g * 64 + n) * 32 + j * 8;
                    *(uint2*)(d)             = make_uint2(h0, h1);
                    *(uint2*)(d + PLANE)     = make_uint2(m0, m1);
                    *(uint2*)(d + 2 * PLANE) = make_uint2(l0, l1);
                }
            }
            __syncthreads();
        }
    }

    // ---- epilogue: per-row top-2 + softmax, register-only + shfl merge ----
#pragma unroll
    for (int half = 0; half < 2; half++) {
        float m1 = -3.4e38f, m2 = -3.4e38f;
        int i1 = 0, i2 = 0;
#pragma unroll
        for (int t = 0; t < 8; t++) {
#pragma unroll
            for (int c = 0; c < 2; c++) {
                float v = acc[t][half * 2 + c];
                int e = 8 * t + 2 * j + c;
                if (v > m1) { m2 = m1; i2 = i1; m1 = v; i1 = e; }
                else if (v > m2) { m2 = v; i2 = e; }
            }
        }
#pragma unroll
        for (int off = 1; off <= 2; off <<= 1) {
            float om1 = __shfl_xor_sync(0xffffffffu, m1, off);
            float om2 = __shfl_xor_sync(0xffffffffu, m2, off);
            int   oi1 = __shfl_xor_sync(0xffffffffu, i1, off);
            int   oi2 = __shfl_xor_sync(0xffffffffu, i2, off);
            if (om1 > m1) {
                float nm2 = (om2 > m1) ? om2 : m1;
                int   ni2 = (om2 > m1) ? oi2 : i1;
                m1 = om1; i1 = oi1; m2 = nm2; i2 = ni2;
            } else if (om1 > m2) {
                m2 = om1; i2 = oi1;
            }
        }
        if (j == 0) {
            int tok = tok0 + warp * 16 + qr + half * 8;
            float ex = __expf(m2 - m1);
            float s1 = 1.0f / (1.0f + ex);
            out[2 * tok]     = s1;
            out[2 * tok + 1] = ex * s1;
            out[2 * NTOK + 2 * tok]     = (float)i1;
            out[2 * NTOK + 2 * tok + 1] = (float)i2;
        }
    }
}

extern "C" void kernel_launch(void* const* d_in, const int* in_sizes, int n_in,
                              void* d_out, int out_size)
{
    const float* hs = (const float*)d_in[0];   // (4, 4096, 4096) fp32
    const float* W  = (const float*)d_in[1];   // (64, 4096) fp32
    float* out      = (float*)d_out;           // [scores 32768][indices 32768]
    (void)in_sizes; (void)n_in; (void)out_size;

    topk_router_kernel<<<NTOK / TOK_CTA, NTHREADS>>>(hs, W, out);
}